// round 1
// baseline (speedup 1.0000x reference)
#include <cuda_runtime.h>
#include <math.h>

// Problem constants
#define N_RAYS    4096
#define N_SAMP    256
#define RES       128
#define RES2      16384      // 128*128
#define RES3      2097152    // 128^3
#define RGB_C     15
#define NEARV     0.2f
#define FARV      3.0f
#define DT        (2.8f/255.0f)
#define ACT_SHIFT (-4.5951198501345895f)   // log(1/(1-0.01)-1)

// Shared layout (floats)
#define OFF_W0   0        // 54*64 = 3456
#define OFF_B0   3456     // 64
#define OFF_W1   3520     // 4096
#define OFF_B1   7616     // 64
#define OFF_W2   7680     // 4096
#define OFF_B2   11776    // 64
#define OFF_W3   11840    // 192
#define OFF_B3   12032    // 3 (+1 pad)
#define OFF_SCAN 12036    // 256
#define OFF_RED  12292    // 64
#define SMEM_FLOATS 12356
#define SMEM_BYTES  (SMEM_FLOATS*4)

// Output offsets (floats)
#define OUT_RGB   0
#define OUT_DEPTH 12288
#define OUT_DISP  16384
#define OUT_ACC   20480
#define OUT_NRM   24576
#define OUT_W     36864
#define OUT_AINV  1085440   // 36864 + 4096*256

__device__ __forceinline__ float tri8(const float* __restrict__ g,
    int i000,int i100,int i010,int i001,int i110,int i101,int i011,int i111,
    float w000,float w100,float w010,float w001,float w110,float w101,float w011,float w111)
{
    return __ldg(g+i000)*w000 + __ldg(g+i100)*w100 + __ldg(g+i010)*w010 + __ldg(g+i001)*w001
         + __ldg(g+i110)*w110 + __ldg(g+i101)*w101 + __ldg(g+i011)*w011 + __ldg(g+i111)*w111;
}

// h[j] += f * wrow[j], j = 0..63, via broadcast LDS.128
__device__ __forceinline__ void accrow(const float* __restrict__ wrow, float f, float (&h)[64])
{
#pragma unroll
    for (int j = 0; j < 16; ++j) {
        float4 w = *reinterpret_cast<const float4*>(wrow + 4*j);
        h[4*j+0] = fmaf(f, w.x, h[4*j+0]);
        h[4*j+1] = fmaf(f, w.y, h[4*j+1]);
        h[4*j+2] = fmaf(f, w.z, h[4*j+2]);
        h[4*j+3] = fmaf(f, w.w, h[4*j+3]);
    }
}

__global__ void __launch_bounds__(256, 1) nerf_fused(
    const float* __restrict__ rays_o, const float* __restrict__ rays_d,
    const float* __restrict__ viewdirs,
    const float* __restrict__ lat_grid, const float* __restrict__ nrm_grid,
    const float* __restrict__ W0, const float* __restrict__ b0,
    const float* __restrict__ W1, const float* __restrict__ b1,
    const float* __restrict__ W2, const float* __restrict__ b2,
    const float* __restrict__ W3, const float* __restrict__ b3,
    float* __restrict__ out)
{
    extern __shared__ float sm[];
    const int tid = threadIdx.x;
    const int ray = blockIdx.x;

    // ---- cooperative weight load into shared ----
    for (int i = tid; i < 3456; i += 256) sm[OFF_W0 + i] = W0[i];
    for (int i = tid; i < 4096; i += 256) { sm[OFF_W1 + i] = W1[i]; sm[OFF_W2 + i] = W2[i]; }
    if (tid < 192) sm[OFF_W3 + tid] = W3[tid];
    if (tid < 64) { sm[OFF_B0 + tid] = b0[tid]; sm[OFF_B1 + tid] = b1[tid]; sm[OFF_B2 + tid] = b2[tid]; }
    if (tid < 3)  sm[OFF_B3 + tid] = b3[tid];
    __syncthreads();

    // ---- per-ray data ----
    float ox = rays_o[ray*3+0], oy = rays_o[ray*3+1], oz = rays_o[ray*3+2];
    float dx = rays_d[ray*3+0], dy = rays_d[ray*3+1], dz = rays_d[ray*3+2];
    {
        float inv = 1.0f / sqrtf(dx*dx + dy*dy + dz*dz);
        dx *= inv; dy *= inv; dz *= inv;
    }
    float vx = viewdirs[ray*3+0], vy = viewdirs[ray*3+1], vz = viewdirs[ray*3+2];
    {
        float inv = 1.0f / sqrtf(vx*vx + vy*vy + vz*vz);
        vx *= inv; vy *= inv; vz *= inv;
    }

    const float t  = NEARV + (float)tid * DT;
    const float px = fmaf(dx, t, ox);
    const float py = fmaf(dy, t, oy);
    const float pz = fmaf(dz, t, oz);

    const bool inb = (px >= -1.0f) & (px <= 1.0f) &
                     (py >= -1.0f) & (py <= 1.0f) &
                     (pz >= -1.0f) & (pz <= 1.0f);

    float alpha = 0.0f;
    float n0 = 0.0f, n1 = 0.0f, n2 = 0.0f;
    float cr = 0.0f, cg = 0.0f, cb = 0.0f;

    if (inb) {
        // ---- trilinear setup ----
        float ux = fminf(fmaxf((px + 1.0f) * 0.5f, 0.0f), 1.0f) * 127.0f;
        float uy = fminf(fmaxf((py + 1.0f) * 0.5f, 0.0f), 1.0f) * 127.0f;
        float uz = fminf(fmaxf((pz + 1.0f) * 0.5f, 0.0f), 1.0f) * 127.0f;
        int ix = min((int)ux, 126), iy = min((int)uy, 126), iz = min((int)uz, 126);
        float fx = ux - (float)ix, fy = uy - (float)iy, fz = uz - (float)iz;
        float gx = 1.0f - fx, gy = 1.0f - fy, gz = 1.0f - fz;

        float w000 = gx*gy*gz, w100 = fx*gy*gz, w010 = gx*fy*gz, w001 = gx*gy*fz;
        float w110 = fx*fy*gz, w101 = fx*gy*fz, w011 = gx*fy*fz, w111 = fx*fy*fz;

        int base = ix*RES2 + iy*RES + iz;
        int i000 = base,            i100 = base + RES2;
        int i010 = base + RES,      i001 = base + 1;
        int i110 = base + RES2+RES, i101 = base + RES2+1;
        int i011 = base + RES+1,    i111 = base + RES2+RES+1;

        // density (latent channel 0)
        float density = tri8(lat_grid, i000,i100,i010,i001,i110,i101,i011,i111,
                             w000,w100,w010,w001,w110,w101,w011,w111);
        // normals
        n0 = tri8(nrm_grid,          i000,i100,i010,i001,i110,i101,i011,i111,
                  w000,w100,w010,w001,w110,w101,w011,w111);
        n1 = tri8(nrm_grid + RES3,   i000,i100,i010,i001,i110,i101,i011,i111,
                  w000,w100,w010,w001,w110,w101,w011,w111);
        n2 = tri8(nrm_grid + 2*RES3, i000,i100,i010,i001,i110,i101,i011,i111,
                  w000,w100,w010,w001,w110,w101,w011,w111);
        {
            float nn = sqrtf(n0*n0 + n1*n1 + n2*n2);
            float inv = 1.0f / fmaxf(nn, 1e-12f);
            n0 *= inv; n1 *= inv; n2 *= inv;
        }

        // alpha
        {
            float z = density + ACT_SHIFT;
            float sp = (z > 15.0f) ? z : log1pf(expf(z));
            alpha = -expm1f(-sp * 0.5f);
        }

        // reflected direction
        float dt0 = -(vx*n0 + vy*n1 + vz*n2);
        float rx = fmaf(2.0f*dt0, n0, vx);
        float ry = fmaf(2.0f*dt0, n1, vy);
        float rz = fmaf(2.0f*dt0, n2, vz);

        // ---- MLP layer 0: stream feat elements into 64 accumulators ----
        float A[64];
#pragma unroll
        for (int j = 0; j < 16; ++j) {
            float4 w = *reinterpret_cast<const float4*>(sm + OFF_B0 + 4*j);
            A[4*j+0] = w.x; A[4*j+1] = w.y; A[4*j+2] = w.z; A[4*j+3] = w.w;
        }
        // latent channels 1..15  -> feat rows 0..14
#pragma unroll
        for (int c = 1; c < 16; ++c) {
            float f = tri8(lat_grid + c*RES3, i000,i100,i010,i001,i110,i101,i011,i111,
                           w000,w100,w010,w001,w110,w101,w011,w111);
            accrow(sm + OFF_W0 + (c-1)*64, f, A);
        }
        // refdir xyz -> rows 15..17
        accrow(sm + OFF_W0 + 15*64, rx, A);
        accrow(sm + OFF_W0 + 16*64, ry, A);
        accrow(sm + OFF_W0 + 17*64, rz, A);
        // sin rows 18..35, cos rows 36..53 (freq-major, coord-minor)
#pragma unroll
        for (int fi = 0; fi < 6; ++fi) {
            float fr = (float)(1 << fi);
            float s, c;
            sincosf(fr*rx, &s, &c);
            accrow(sm + OFF_W0 + (18 + fi*3 + 0)*64, s, A);
            accrow(sm + OFF_W0 + (36 + fi*3 + 0)*64, c, A);
            sincosf(fr*ry, &s, &c);
            accrow(sm + OFF_W0 + (18 + fi*3 + 1)*64, s, A);
            accrow(sm + OFF_W0 + (36 + fi*3 + 1)*64, c, A);
            sincosf(fr*rz, &s, &c);
            accrow(sm + OFF_W0 + (18 + fi*3 + 2)*64, s, A);
            accrow(sm + OFF_W0 + (36 + fi*3 + 2)*64, c, A);
        }
#pragma unroll
        for (int j = 0; j < 64; ++j) A[j] = fmaxf(A[j], 0.0f);

        // ---- layer 1 ----
        float B[64];
#pragma unroll
        for (int j = 0; j < 16; ++j) {
            float4 w = *reinterpret_cast<const float4*>(sm + OFF_B1 + 4*j);
            B[4*j+0] = w.x; B[4*j+1] = w.y; B[4*j+2] = w.z; B[4*j+3] = w.w;
        }
#pragma unroll
        for (int k = 0; k < 64; ++k) accrow(sm + OFF_W1 + k*64, A[k], B);
#pragma unroll
        for (int j = 0; j < 64; ++j) B[j] = fmaxf(B[j], 0.0f);

        // ---- layer 2 (reuse A) ----
#pragma unroll
        for (int j = 0; j < 16; ++j) {
            float4 w = *reinterpret_cast<const float4*>(sm + OFF_B2 + 4*j);
            A[4*j+0] = w.x; A[4*j+1] = w.y; A[4*j+2] = w.z; A[4*j+3] = w.w;
        }
#pragma unroll
        for (int k = 0; k < 64; ++k) accrow(sm + OFF_W2 + k*64, B[k], A);
#pragma unroll
        for (int j = 0; j < 64; ++j) A[j] = fmaxf(A[j], 0.0f);

        // ---- layer 3 + sigmoid ----
        float o0 = sm[OFF_B3+0], o1 = sm[OFF_B3+1], o2 = sm[OFF_B3+2];
#pragma unroll
        for (int k = 0; k < 64; ++k) {
            float f = A[k];
            o0 = fmaf(f, sm[OFF_W3 + k*3+0], o0);
            o1 = fmaf(f, sm[OFF_W3 + k*3+1], o1);
            o2 = fmaf(f, sm[OFF_W3 + k*3+2], o2);
        }
        cr = 1.0f / (1.0f + expf(-o0));
        cg = 1.0f / (1.0f + expf(-o1));
        cb = 1.0f / (1.0f + expf(-o2));
    }

    // ---- inclusive product scan of clipped (1-alpha) ----
    float* sScan = sm + OFF_SCAN;
    float ac = fmaxf(1.0f - alpha, 1e-10f);
    sScan[tid] = ac;
    __syncthreads();
#pragma unroll
    for (int off = 1; off < 256; off <<= 1) {
        float v = (tid >= off) ? sScan[tid - off] : 1.0f;
        __syncthreads();
        sScan[tid] *= v;
        __syncthreads();
    }
    float excl = (tid == 0) ? 1.0f : sScan[tid - 1];
    float w = alpha * excl;

    // ---- per-sample outputs ----
    out[OUT_W    + ray*N_SAMP + tid]       = w;
    out[OUT_AINV + ray*257   + tid + 1]    = sScan[tid];
    if (tid == 0) out[OUT_AINV + ray*257]  = 1.0f;

    // ---- marching reductions: [w, w*t, w*rgb(3), w*nrm(3)] ----
    float vals[8] = { w, w*t, w*cr, w*cg, w*cb, w*n0, w*n1, w*n2 };
#pragma unroll
    for (int q = 0; q < 8; ++q) {
        float v = vals[q];
#pragma unroll
        for (int off = 16; off > 0; off >>= 1)
            v += __shfl_down_sync(0xFFFFFFFFu, v, off);
        vals[q] = v;
    }
    float* sRed = sm + OFF_RED;
    int warp = tid >> 5, lane = tid & 31;
    if (lane == 0) {
#pragma unroll
        for (int q = 0; q < 8; ++q) sRed[warp*8 + q] = vals[q];
    }
    __syncthreads();
    if (tid == 0) {
        float s[8];
#pragma unroll
        for (int q = 0; q < 8; ++q) s[q] = 0.0f;
        for (int wi = 0; wi < 8; ++wi)
#pragma unroll
            for (int q = 0; q < 8; ++q) s[q] += sRed[wi*8 + q];
        float Tf = sScan[255];
        out[OUT_RGB + ray*3+0] = s[2] + Tf;       // BG = 1.0
        out[OUT_RGB + ray*3+1] = s[3] + Tf;
        out[OUT_RGB + ray*3+2] = s[4] + Tf;
        float dmar = s[1] + Tf * FARV;
        out[OUT_DEPTH + ray] = dmar;
        out[OUT_DISP  + ray] = 1.0f / dmar;
        out[OUT_ACC   + ray] = s[0];
        out[OUT_NRM + ray*3+0] = s[5];
        out[OUT_NRM + ray*3+1] = s[6];
        out[OUT_NRM + ray*3+2] = s[7];
    }
}

extern "C" void kernel_launch(void* const* d_in, const int* in_sizes, int n_in,
                              void* d_out, int out_size)
{
    const float* rays_o   = (const float*)d_in[0];
    const float* rays_d   = (const float*)d_in[1];
    const float* viewdirs = (const float*)d_in[2];
    const float* lat      = (const float*)d_in[3];
    const float* nrm      = (const float*)d_in[4];
    const float* W0 = (const float*)d_in[5];
    const float* b0 = (const float*)d_in[6];
    const float* W1 = (const float*)d_in[7];
    const float* b1 = (const float*)d_in[8];
    const float* W2 = (const float*)d_in[9];
    const float* b2 = (const float*)d_in[10];
    const float* W3 = (const float*)d_in[11];
    const float* b3 = (const float*)d_in[12];
    float* out = (float*)d_out;

    cudaFuncSetAttribute(nerf_fused, cudaFuncAttributeMaxDynamicSharedMemorySize, SMEM_BYTES);
    nerf_fused<<<N_RAYS, N_SAMP, SMEM_BYTES>>>(
        rays_o, rays_d, viewdirs, lat, nrm,
        W0, b0, W1, b1, W2, b2, W3, b3, out);
}

// round 2
// speedup vs baseline: 2.5402x; 2.5402x over previous
#include <cuda_runtime.h>
#include <math.h>

// Problem constants
#define N_RAYS    4096
#define N_SAMP    256
#define NT        (N_RAYS*N_SAMP)   // 1048576
#define RES       128
#define RES2      16384
#define RES3      2097152
#define NEARV     0.2f
#define FARV      3.0f
#define DT        (2.8f/255.0f)
#define ACT_SHIFT (-4.5951198501345895f)

// Output offsets (floats)
#define OUT_RGB   0
#define OUT_DEPTH 12288
#define OUT_DISP  16384
#define OUT_ACC   20480
#define OUT_NRM   24576
#define OUT_W     36864
#define OUT_AINV  1085440   // 36864 + 4096*256

// MLP weight smem layout (floats)
#define OFF_W0   0        // 54*64
#define OFF_B0   3456
#define OFF_W1   3520
#define OFF_B1   7616
#define OFF_W2   7680
#define OFF_B2   11776
#define OFF_W3   11840
#define OFF_B3   12032    // 3 + 1 pad
#define W_FLOATS 12036

// ---- global scratch (no allocation allowed) ----
__device__ float g_lat[15*NT];   // SoA [ch][sample] : latent channels 1..15
__device__ float g_ref[3*NT];    // SoA refdir
__device__ float g_rgbw[3*NT];   // SoA w*rgb

// ============================================================
// helpers
// ============================================================
__device__ __forceinline__ float tri8(const float* __restrict__ g,
    int i000,int i100,int i010,int i001,int i110,int i101,int i011,int i111,
    float w000,float w100,float w010,float w001,float w110,float w101,float w011,float w111)
{
    return __ldg(g+i000)*w000 + __ldg(g+i100)*w100 + __ldg(g+i010)*w010 + __ldg(g+i001)*w001
         + __ldg(g+i110)*w110 + __ldg(g+i101)*w101 + __ldg(g+i011)*w011 + __ldg(g+i111)*w111;
}

__device__ __forceinline__ unsigned long long dup2(float f) {
    unsigned long long r;
    asm("mov.b64 %0, {%1, %1};" : "=l"(r) : "f"(f));
    return r;
}
__device__ __forceinline__ void fma2(unsigned long long &d, unsigned long long a, unsigned long long b) {
    asm("fma.rn.f32x2 %0, %1, %2, %0;" : "+l"(d) : "l"(a), "l"(b));
}
__device__ __forceinline__ float2 unpk(unsigned long long v) {
    float2 r;
    asm("mov.b64 {%0, %1}, %2;" : "=f"(r.x), "=f"(r.y) : "l"(v));
    return r;
}

// h[j] (packed pairs, 32 regs of f32x2) += f * wrow[0..63]
__device__ __forceinline__ void accrow2(const float* __restrict__ wrow,
                                        unsigned long long f2,
                                        unsigned long long (&h)[32])
{
#pragma unroll
    for (int j = 0; j < 16; ++j) {
        ulonglong2 w = *reinterpret_cast<const ulonglong2*>(wrow + 4*j);
        fma2(h[2*j+0], f2, w.x);
        fma2(h[2*j+1], f2, w.y);
    }
}

// ============================================================
// Kernel 1: gather + alpha + scan + all non-rgb outputs; stash feat pieces
// ============================================================
__global__ void __launch_bounds__(256) k1_gather(
    const float* __restrict__ rays_o, const float* __restrict__ rays_d,
    const float* __restrict__ viewdirs,
    const float* __restrict__ lat_grid, const float* __restrict__ nrm_grid,
    float* __restrict__ out)
{
    __shared__ float sScan[256];
    __shared__ float sRed[64];
    const int tid = threadIdx.x;
    const int ray = blockIdx.x;
    const int gs  = ray*N_SAMP + tid;

    float ox = rays_o[ray*3+0], oy = rays_o[ray*3+1], oz = rays_o[ray*3+2];
    float dx = rays_d[ray*3+0], dy = rays_d[ray*3+1], dz = rays_d[ray*3+2];
    { float inv = 1.0f/sqrtf(dx*dx+dy*dy+dz*dz); dx*=inv; dy*=inv; dz*=inv; }
    float vx = viewdirs[ray*3+0], vy = viewdirs[ray*3+1], vz = viewdirs[ray*3+2];
    { float inv = 1.0f/sqrtf(vx*vx+vy*vy+vz*vz); vx*=inv; vy*=inv; vz*=inv; }

    const float t  = NEARV + (float)tid * DT;
    const float px = fmaf(dx, t, ox);
    const float py = fmaf(dy, t, oy);
    const float pz = fmaf(dz, t, oz);
    const bool inb = (px >= -1.0f) & (px <= 1.0f) &
                     (py >= -1.0f) & (py <= 1.0f) &
                     (pz >= -1.0f) & (pz <= 1.0f);

    float alpha = 0.0f, n0 = 0.0f, n1 = 0.0f, n2 = 0.0f;

    if (inb) {
        float ux = fminf(fmaxf((px+1.0f)*0.5f,0.0f),1.0f)*127.0f;
        float uy = fminf(fmaxf((py+1.0f)*0.5f,0.0f),1.0f)*127.0f;
        float uz = fminf(fmaxf((pz+1.0f)*0.5f,0.0f),1.0f)*127.0f;
        int ix = min((int)ux,126), iy = min((int)uy,126), iz = min((int)uz,126);
        float fx = ux-(float)ix, fy = uy-(float)iy, fz = uz-(float)iz;
        float gx = 1.0f-fx, gy = 1.0f-fy, gz = 1.0f-fz;
        float w000=gx*gy*gz, w100=fx*gy*gz, w010=gx*fy*gz, w001=gx*gy*fz;
        float w110=fx*fy*gz, w101=fx*gy*fz, w011=gx*fy*fz, w111=fx*fy*fz;

        int base = ix*RES2 + iy*RES + iz;
        int i000=base,            i100=base+RES2;
        int i010=base+RES,        i001=base+1;
        int i110=base+RES2+RES,   i101=base+RES2+1;
        int i011=base+RES+1,      i111=base+RES2+RES+1;

        float density = tri8(lat_grid, i000,i100,i010,i001,i110,i101,i011,i111,
                             w000,w100,w010,w001,w110,w101,w011,w111);
        n0 = tri8(nrm_grid,        i000,i100,i010,i001,i110,i101,i011,i111,
                  w000,w100,w010,w001,w110,w101,w011,w111);
        n1 = tri8(nrm_grid+RES3,   i000,i100,i010,i001,i110,i101,i011,i111,
                  w000,w100,w010,w001,w110,w101,w011,w111);
        n2 = tri8(nrm_grid+2*RES3, i000,i100,i010,i001,i110,i101,i011,i111,
                  w000,w100,w010,w001,w110,w101,w011,w111);
        {
            float nn = sqrtf(n0*n0+n1*n1+n2*n2);
            float inv = 1.0f/fmaxf(nn, 1e-12f);
            n0*=inv; n1*=inv; n2*=inv;
        }
        {
            float z = density + ACT_SHIFT;
            float sp = (z > 15.0f) ? z : log1pf(expf(z));
            alpha = -expm1f(-sp*0.5f);
        }
        // reflected dir
        float dt0 = -(vx*n0 + vy*n1 + vz*n2);
        g_ref[0*NT+gs] = fmaf(2.0f*dt0, n0, vx);
        g_ref[1*NT+gs] = fmaf(2.0f*dt0, n1, vy);
        g_ref[2*NT+gs] = fmaf(2.0f*dt0, n2, vz);
        // latent channels 1..15
#pragma unroll
        for (int c = 1; c < 16; ++c) {
            float f = tri8(lat_grid + c*RES3, i000,i100,i010,i001,i110,i101,i011,i111,
                           w000,w100,w010,w001,w110,w101,w011,w111);
            g_lat[(c-1)*NT + gs] = f;
        }
    }

    // inclusive product scan of clipped (1-alpha)
    float ac = fmaxf(1.0f - alpha, 1e-10f);
    sScan[tid] = ac;
    __syncthreads();
#pragma unroll
    for (int off = 1; off < 256; off <<= 1) {
        float v = (tid >= off) ? sScan[tid - off] : 1.0f;
        __syncthreads();
        sScan[tid] *= v;
        __syncthreads();
    }
    float excl = (tid == 0) ? 1.0f : sScan[tid - 1];
    float w = alpha * excl;

    out[OUT_W    + gs]               = w;
    out[OUT_AINV + ray*257 + tid+1]  = sScan[tid];
    if (tid == 0) out[OUT_AINV + ray*257] = 1.0f;

    // reductions: [w, w*t, w*n0, w*n1, w*n2]
    float vals[5] = { w, w*t, w*n0, w*n1, w*n2 };
#pragma unroll
    for (int q = 0; q < 5; ++q) {
        float v = vals[q];
#pragma unroll
        for (int off = 16; off > 0; off >>= 1)
            v += __shfl_down_sync(0xFFFFFFFFu, v, off);
        vals[q] = v;
    }
    int warp = tid >> 5, lane = tid & 31;
    if (lane == 0) {
#pragma unroll
        for (int q = 0; q < 5; ++q) sRed[warp*8+q] = vals[q];
    }
    __syncthreads();
    if (tid == 0) {
        float s[5] = {0,0,0,0,0};
        for (int wi = 0; wi < 8; ++wi)
#pragma unroll
            for (int q = 0; q < 5; ++q) s[q] += sRed[wi*8+q];
        float dmar = s[1] + sScan[255]*FARV;
        out[OUT_DEPTH + ray] = dmar;
        out[OUT_DISP  + ray] = 1.0f/dmar;
        out[OUT_ACC   + ray] = s[0];
        out[OUT_NRM + ray*3+0] = s[2];
        out[OUT_NRM + ray*3+1] = s[3];
        out[OUT_NRM + ray*3+2] = s[4];
    }
}

// ============================================================
// Kernel 2: MLP (grid-stride over samples; f32x2 packed FMAs)
// ============================================================
__global__ void __launch_bounds__(128, 3) k2_mlp(
    const float* __restrict__ rays_o, const float* __restrict__ rays_d,
    const float* __restrict__ W0, const float* __restrict__ b0,
    const float* __restrict__ W1, const float* __restrict__ b1,
    const float* __restrict__ W2, const float* __restrict__ b2,
    const float* __restrict__ W3, const float* __restrict__ b3,
    const float* __restrict__ outw)  // = d_out (weights written by k1)
{
    __shared__ float sm[W_FLOATS];
    const int tid = threadIdx.x;
    for (int i = tid; i < 3456; i += 128) sm[OFF_W0+i] = W0[i];
    for (int i = tid; i < 4096; i += 128) { sm[OFF_W1+i] = W1[i]; sm[OFF_W2+i] = W2[i]; }
    for (int i = tid; i < 192; i += 128) sm[OFF_W3+i] = W3[i];
    if (tid < 64) { sm[OFF_B0+tid]=b0[tid]; sm[OFF_B1+tid]=b1[tid]; sm[OFF_B2+tid]=b2[tid]; }
    if (tid < 3)  sm[OFF_B3+tid]=b3[tid];
    __syncthreads();

    const int s   = blockIdx.x * 128 + tid;
    const int ray = s >> 8;
    const int sid = s & 255;

    // recompute in-bbox test
    float ox = __ldg(rays_o+ray*3+0), oy = __ldg(rays_o+ray*3+1), oz = __ldg(rays_o+ray*3+2);
    float dx = __ldg(rays_d+ray*3+0), dy = __ldg(rays_d+ray*3+1), dz = __ldg(rays_d+ray*3+2);
    { float inv = 1.0f/sqrtf(dx*dx+dy*dy+dz*dz); dx*=inv; dy*=inv; dz*=inv; }
    const float t  = NEARV + (float)sid * DT;
    const float px = fmaf(dx,t,ox), py = fmaf(dy,t,oy), pz = fmaf(dz,t,oz);
    const bool inb = (px>=-1.0f)&(px<=1.0f)&(py>=-1.0f)&(py<=1.0f)&(pz>=-1.0f)&(pz<=1.0f);

    if (!inb) {
        g_rgbw[0*NT+s]=0.0f; g_rgbw[1*NT+s]=0.0f; g_rgbw[2*NT+s]=0.0f;
        return;
    }

    float rx = g_ref[0*NT+s], ry = g_ref[1*NT+s], rz = g_ref[2*NT+s];

    // ---- layer 0 ----
    unsigned long long h[32];
#pragma unroll
    for (int j = 0; j < 16; ++j) {
        ulonglong2 b = *reinterpret_cast<const ulonglong2*>(sm + OFF_B0 + 4*j);
        h[2*j] = b.x; h[2*j+1] = b.y;
    }
#pragma unroll
    for (int c = 0; c < 15; ++c)
        accrow2(sm + OFF_W0 + c*64, dup2(g_lat[c*NT+s]), h);
    accrow2(sm + OFF_W0 + 15*64, dup2(rx), h);
    accrow2(sm + OFF_W0 + 16*64, dup2(ry), h);
    accrow2(sm + OFF_W0 + 17*64, dup2(rz), h);
#pragma unroll
    for (int fi = 0; fi < 6; ++fi) {
        float fr = (float)(1 << fi);
        float sn, cs;
        __sincosf(fr*rx, &sn, &cs);
        accrow2(sm + OFF_W0 + (18+fi*3+0)*64, dup2(sn), h);
        accrow2(sm + OFF_W0 + (36+fi*3+0)*64, dup2(cs), h);
        __sincosf(fr*ry, &sn, &cs);
        accrow2(sm + OFF_W0 + (18+fi*3+1)*64, dup2(sn), h);
        accrow2(sm + OFF_W0 + (36+fi*3+1)*64, dup2(cs), h);
        __sincosf(fr*rz, &sn, &cs);
        accrow2(sm + OFF_W0 + (18+fi*3+2)*64, dup2(sn), h);
        accrow2(sm + OFF_W0 + (36+fi*3+2)*64, dup2(cs), h);
    }

    float A[64];
#pragma unroll
    for (int j = 0; j < 32; ++j) {
        float2 v = unpk(h[j]);
        A[2*j+0] = fmaxf(v.x, 0.0f);
        A[2*j+1] = fmaxf(v.y, 0.0f);
    }

    // ---- layer 1 ----
#pragma unroll
    for (int j = 0; j < 16; ++j) {
        ulonglong2 b = *reinterpret_cast<const ulonglong2*>(sm + OFF_B1 + 4*j);
        h[2*j] = b.x; h[2*j+1] = b.y;
    }
#pragma unroll
    for (int k = 0; k < 64; ++k)
        accrow2(sm + OFF_W1 + k*64, dup2(A[k]), h);
#pragma unroll
    for (int j = 0; j < 32; ++j) {
        float2 v = unpk(h[j]);
        A[2*j+0] = fmaxf(v.x, 0.0f);
        A[2*j+1] = fmaxf(v.y, 0.0f);
    }

    // ---- layer 2 ----
#pragma unroll
    for (int j = 0; j < 16; ++j) {
        ulonglong2 b = *reinterpret_cast<const ulonglong2*>(sm + OFF_B2 + 4*j);
        h[2*j] = b.x; h[2*j+1] = b.y;
    }
#pragma unroll
    for (int k = 0; k < 64; ++k)
        accrow2(sm + OFF_W2 + k*64, dup2(A[k]), h);
#pragma unroll
    for (int j = 0; j < 32; ++j) {
        float2 v = unpk(h[j]);
        A[2*j+0] = fmaxf(v.x, 0.0f);
        A[2*j+1] = fmaxf(v.y, 0.0f);
    }

    // ---- layer 3 + sigmoid ----
    float o0 = sm[OFF_B3+0], o1 = sm[OFF_B3+1], o2 = sm[OFF_B3+2];
#pragma unroll
    for (int k = 0; k < 64; ++k) {
        float f = A[k];
        o0 = fmaf(f, sm[OFF_W3 + k*3+0], o0);
        o1 = fmaf(f, sm[OFF_W3 + k*3+1], o1);
        o2 = fmaf(f, sm[OFF_W3 + k*3+2], o2);
    }
    float cr = 1.0f/(1.0f + __expf(-o0));
    float cg = 1.0f/(1.0f + __expf(-o1));
    float cb = 1.0f/(1.0f + __expf(-o2));

    float w = __ldg(outw + OUT_W + s);
    g_rgbw[0*NT+s] = w*cr;
    g_rgbw[1*NT+s] = w*cg;
    g_rgbw[2*NT+s] = w*cb;
}

// ============================================================
// Kernel 3: rgb march reduction (block per ray)
// ============================================================
__global__ void __launch_bounds__(256) k3_rgb(float* __restrict__ out)
{
    __shared__ float sRed[32];
    const int tid = threadIdx.x;
    const int ray = blockIdx.x;
    const int gs  = ray*N_SAMP + tid;

    float vr = g_rgbw[0*NT+gs];
    float vg = g_rgbw[1*NT+gs];
    float vb = g_rgbw[2*NT+gs];
#pragma unroll
    for (int off = 16; off > 0; off >>= 1) {
        vr += __shfl_down_sync(0xFFFFFFFFu, vr, off);
        vg += __shfl_down_sync(0xFFFFFFFFu, vg, off);
        vb += __shfl_down_sync(0xFFFFFFFFu, vb, off);
    }
    int warp = tid >> 5, lane = tid & 31;
    if (lane == 0) { sRed[warp*4+0]=vr; sRed[warp*4+1]=vg; sRed[warp*4+2]=vb; }
    __syncthreads();
    if (tid == 0) {
        float sr=0, sg=0, sb=0;
        for (int wi = 0; wi < 8; ++wi) { sr+=sRed[wi*4+0]; sg+=sRed[wi*4+1]; sb+=sRed[wi*4+2]; }
        float T = out[OUT_AINV + ray*257 + 256];
        out[OUT_RGB + ray*3+0] = sr + T;   // BG = 1.0
        out[OUT_RGB + ray*3+1] = sg + T;
        out[OUT_RGB + ray*3+2] = sb + T;
    }
}

// ============================================================
extern "C" void kernel_launch(void* const* d_in, const int* in_sizes, int n_in,
                              void* d_out, int out_size)
{
    const float* rays_o   = (const float*)d_in[0];
    const float* rays_d   = (const float*)d_in[1];
    const float* viewdirs = (const float*)d_in[2];
    const float* lat      = (const float*)d_in[3];
    const float* nrm      = (const float*)d_in[4];
    const float* W0 = (const float*)d_in[5];
    const float* b0 = (const float*)d_in[6];
    const float* W1 = (const float*)d_in[7];
    const float* b1 = (const float*)d_in[8];
    const float* W2 = (const float*)d_in[9];
    const float* b2 = (const float*)d_in[10];
    const float* W3 = (const float*)d_in[11];
    const float* b3 = (const float*)d_in[12];
    float* out = (float*)d_out;

    k1_gather<<<N_RAYS, 256>>>(rays_o, rays_d, viewdirs, lat, nrm, out);
    k2_mlp<<<NT/128, 128>>>(rays_o, rays_d, W0, b0, W1, b1, W2, b2, W3, b3, out);
    k3_rgb<<<N_RAYS, 256>>>(out);
}